// round 15
// baseline (speedup 1.0000x reference)
#include <cuda_runtime.h>
#include <cuda_fp16.h>
#include <math.h>

// Problem constants (from reference setup_inputs)
#define BB 2
#define HH 256
#define WW 256
#define DD 128
#define D3 (DD * DD * DD)
#define DT 0.03125f
#define NSTEPS 111

// z-slab pipeline: volume split into 8 chunks of 16 z-slices per batch.
// Chunk ids are interleaved across batches: g = 2*c + b (both batches
// progress together). g_done[g] counts completed interleave blocks (256 per
// chunk), monotone across graph replays; reset_kernel snapshots per-replay
// targets. rm polls chunks IN ORDER so every slab <= the confirmed chunk is
// published (release via threadfence+atomic, acquire via volatile+fence)
// before any rm load touches it.
#define NCHUNK 8
#define BLKS_PER_CHUNK 256
__device__ int g_done[2 * NCHUNK];    // zero-init at module load
__device__ int g_target[2 * NCHUNK];

// Non-redundant half4 volume: entry i (8 B uint2) = voxel i's 4 channels in
// fp16: (r,g),(b,a). Padded by DD*DD+DD+1 zero-initialized entries so
// unclamped-neighbor addresses stay in bounds; such entries are only ever
// multiplied by exactly-zero weights.
__device__ uint2 g_vol[BB * D3 + DD * DD + DD + 1];

__global__ void reset_kernel() {
    int t = threadIdx.x;
    if (t < 2 * NCHUNK) g_target[t] = g_done[t] + BLKS_PER_CHUNK;
}

__device__ __forceinline__ unsigned pack2h(float lo, float hi) {
    __half2 h = __floats2half2_rn(lo, hi);
    return *reinterpret_cast<unsigned*>(&h);
}

// ---------------------------------------------------------------------------
// Pass 1: interleave + fp16-pack, chunk-granular publish. 4096 blocks x 256
// threads; 256 blocks per chunk; chunk order interleaves batches. Dummy
// dynamic smem (set at launch) caps residency at 1 block/SM so the raymarch
// kernel is guaranteed co-residency (no deadlock).
// ---------------------------------------------------------------------------
__global__ void interleave_kernel(const float4* __restrict__ vol4) {
    const int QP = D3 / 4;
    extern __shared__ char dummy_smem[];  // residency limiter (unused)
    int g = blockIdx.x >> 8;              // global chunk id 0..15
    int within = blockIdx.x & 255;
    int b = g & 1;
    int c = g >> 1;
    int s4 = c * (QP / NCHUNK) + within * 256 + threadIdx.x;

    const float4* base4 = vol4 + (long)b * 4 * QP;
    float4 c0 = __ldg(base4 + 0 * QP + s4);
    float4 c1 = __ldg(base4 + 1 * QP + s4);
    float4 c2 = __ldg(base4 + 2 * QP + s4);
    float4 c3 = __ldg(base4 + 3 * QP + s4);

    uint4* outp = reinterpret_cast<uint4*>(g_vol) + ((long)b * D3 / 2 + (long)s4 * 2);
    uint4 u0, u1;
    u0.x = pack2h(c0.x, c1.x); u0.y = pack2h(c2.x, c3.x);   // voxel 4*s4+0
    u0.z = pack2h(c0.y, c1.y); u0.w = pack2h(c2.y, c3.y);   // voxel 4*s4+1
    u1.x = pack2h(c0.z, c1.z); u1.y = pack2h(c2.z, c3.z);   // voxel 4*s4+2
    u1.z = pack2h(c0.w, c1.w); u1.w = pack2h(c2.w, c3.w);   // voxel 4*s4+3
    outp[0] = u0;
    outp[1] = u1;

    // publish: all block stores -> fence -> block barrier -> one counted add
    __threadfence();
    __syncthreads();
    if (threadIdx.x == 0) atomicAdd(&g_done[g], 1);
    (void)dummy_smem;
}

// One pipeline stage: validity, fractions, 8 in-flight corner loads.
struct Stage {
    bool valid;
    float fx, fy, fz;
    uint2 U000, U001, U010, U011, U100, U101, U110, U111;
};

__device__ __forceinline__ void prep_step(
    const uint2* __restrict__ vb,
    float pxp, float pyp, float pzp, Stage& st, int& rc, int b) {
    // valid  <=>  (-1 < p < 1) on all axes  <=>  max|p| < 1   (exact)
    float m = fmaxf(fmaxf(fabsf(pxp), fabsf(pyp)), fabsf(pzp));
    st.valid = m < 1.0f;
    float gx = fmaf(pxp, 63.5f, 63.5f);
    float gy = fmaf(pyp, 63.5f, 63.5f);
    float gz = fmaf(pzp, 63.5f, 63.5f);
    // x/y: single unsigned clamp (negative -> huge -> 127); valid positions
    // give [0,127]; index 127 only reachable with fraction exactly 0.
    int x0 = (int)min((unsigned)__float2int_rd(gx), 127u);
    int y0 = (int)min((unsigned)__float2int_rd(gy), 127u);
    // z: signed clamp so pre-entry (gz<0) maps to slab 0, keeping the
    // pipeline poll monotone from the front of the volume.
    int z0 = min(max(__float2int_rd(gz), 0), 127);
    st.fx = gx - (float)x0;
    st.fy = gy - (float)y0;
    st.fz = gz - (float)z0;

    // pipeline gate: chunk containing row z0+1 must be published. rc =
    // number of confirmed chunks (chunks [0,rc) ready, confirmed IN ORDER).
    int c_need = min((z0 + 1) >> 4, NCHUNK - 1);
    if (rc <= c_need) {
        do {
            int idx = (rc << 1) + b;
            if (((volatile const int*)g_done)[idx] >= g_target[idx]) rc++;
        } while (rc <= c_need);
        __threadfence();  // acquire: order the loads below after the flag
    }

    int base = (((z0 << 7) + y0) << 7) + x0;
    st.U000 = __ldg(vb + base);
    st.U001 = __ldg(vb + base + 1);
    st.U010 = __ldg(vb + base + DD);
    st.U011 = __ldg(vb + base + DD + 1);
    st.U100 = __ldg(vb + base + DD * DD);
    st.U101 = __ldg(vb + base + DD * DD + 1);
    st.U110 = __ldg(vb + base + DD * DD + DD);
    st.U111 = __ldg(vb + base + DD * DD + DD + 1);
}

__device__ __forceinline__ __half2 h2_of(unsigned u) {
    return *reinterpret_cast<const __half2*>(&u);
}

// half2 lerp: a + t*(b-a)
__device__ __forceinline__ __half2 h2lerp(__half2 a, __half2 b, __half2 t) {
    return __hfma2(t, __hsub2(b, a), a);
}

// Branchless consume: fp16 lerp-tree trilerp (x, then y, then z) + fp32
// compositing. The alpha chain is bit-exact unfused _rn (it gates
// saturation); rgb accumulators are smooth terminal outputs, so FFMA
// contraction there is harmless. Contribution gated by validity via one
// select; invalid steps add exact zeros.
__device__ __forceinline__ void consume(const Stage& st,
                                        float& r_out, float& g_out,
                                        float& b_out, float& a_out) {
    __half2 fxh = __float2half2_rn(st.fx);
    __half2 fyh = __float2half2_rn(st.fy);
    __half2 fzh = __float2half2_rn(st.fz);

    __half2 c00rg = h2lerp(h2_of(st.U000.x), h2_of(st.U001.x), fxh);
    __half2 c00ba = h2lerp(h2_of(st.U000.y), h2_of(st.U001.y), fxh);
    __half2 c01rg = h2lerp(h2_of(st.U010.x), h2_of(st.U011.x), fxh);
    __half2 c01ba = h2lerp(h2_of(st.U010.y), h2_of(st.U011.y), fxh);
    __half2 c10rg = h2lerp(h2_of(st.U100.x), h2_of(st.U101.x), fxh);
    __half2 c10ba = h2lerp(h2_of(st.U100.y), h2_of(st.U101.y), fxh);
    __half2 c11rg = h2lerp(h2_of(st.U110.x), h2_of(st.U111.x), fxh);
    __half2 c11ba = h2lerp(h2_of(st.U110.y), h2_of(st.U111.y), fxh);
    __half2 c0rg = h2lerp(c00rg, c01rg, fyh);
    __half2 c0ba = h2lerp(c00ba, c01ba, fyh);
    __half2 c1rg = h2lerp(c10rg, c11rg, fyh);
    __half2 c1ba = h2lerp(c10ba, c11ba, fyh);
    float2 rg = __half22float2(h2lerp(c0rg, c1rg, fzh));
    float2 ba = __half22float2(h2lerp(c0ba, c1ba, fzh));

    float contrib = __fsub_rn(
        fminf(__fadd_rn(a_out, __fmul_rn(ba.y, DT)), 1.0f), a_out);
    contrib = st.valid ? contrib : 0.0f;   // single select, no branch
    r_out = fmaf(rg.x, contrib, r_out);    // smooth: FFMA ok
    g_out = fmaf(rg.y, contrib, g_out);
    b_out = fmaf(ba.x, contrib, b_out);
    a_out = __fadd_rn(a_out, contrib);     // exact: gates saturation
}

// ---------------------------------------------------------------------------
// Pass 2: full-grid ray march (both batches, blockIdx.z = batch), depth-1
// prefetch with ping-pong stages, z-slab flag gating. Occupancy capped at 12
// blocks/SM to guarantee the interleave producer can always co-reside
// (liveness). Ray setup + position stepping replicate the reference's IEEE
// fp32 ops bit-exactly (unfused _rn intrinsics): step-0 validity is a
// knife-edge. Saturation checked once per unrolled pair (alpha saturates to
// exactly 1.0 -> later contribs exactly 0). Phantom steps past kmax are
// geometrically invalid.
// ---------------------------------------------------------------------------
__global__ void __launch_bounds__(64, 12)
raymarch_kernel(const float* __restrict__ camrot,
                const float* __restrict__ campos,
                const float* __restrict__ focal,
                const float* __restrict__ princpt,
                const float* __restrict__ pixelcoords,
                float* __restrict__ out) {
    int x = blockIdx.x * blockDim.x + threadIdx.x;
    int y = blockIdx.y * blockDim.y + threadIdx.y;
    int b = blockIdx.z;

    // --- camera ray (bit-exact vs reference) ---
    long pidx = (((long)b * HH + y) * WW + x) * 2;
    float px = pixelcoords[pidx + 0];
    float py = pixelcoords[pidx + 1];
    float rx = __fdiv_rn(__fsub_rn(px, princpt[b * 2 + 0]), focal[b * 2 + 0]);
    float ry = __fdiv_rn(__fsub_rn(py, princpt[b * 2 + 1]), focal[b * 2 + 1]);
    float rz = 1.0f;
    const float* R = camrot + b * 9;  // dir_j = sum_i R[i][j] * r_i
    float dx = __fadd_rn(__fadd_rn(__fmul_rn(R[0], rx), __fmul_rn(R[3], ry)),
                         __fmul_rn(R[6], rz));
    float dy = __fadd_rn(__fadd_rn(__fmul_rn(R[1], rx), __fmul_rn(R[4], ry)),
                         __fmul_rn(R[7], rz));
    float dz = __fadd_rn(__fadd_rn(__fmul_rn(R[2], rx), __fmul_rn(R[5], ry)),
                         __fmul_rn(R[8], rz));
    float n2 = __fadd_rn(__fadd_rn(__fmul_rn(dx, dx), __fmul_rn(dy, dy)),
                         __fmul_rn(dz, dz));
    float nrm = sqrtf(n2);
    dx = __fdiv_rn(dx, nrm);
    dy = __fdiv_rn(dy, nrm);
    dz = __fdiv_rn(dz, nrm);

    float cx = campos[b * 3 + 0];
    float cy = campos[b * 3 + 1];
    float cz = campos[b * 3 + 2];

    // --- AABB [-1,1]^3 intersection (IEEE divisions; inf semantics ok) ---
    float t1x = __fdiv_rn(__fsub_rn(-1.0f, cx), dx);
    float t2x = __fdiv_rn(__fsub_rn( 1.0f, cx), dx);
    float t1y = __fdiv_rn(__fsub_rn(-1.0f, cy), dy);
    float t2y = __fdiv_rn(__fsub_rn( 1.0f, cy), dy);
    float t1z = __fdiv_rn(__fsub_rn(-1.0f, cz), dz);
    float t2z = __fdiv_rn(__fsub_rn( 1.0f, cz), dz);
    float tmin = fmaxf(fminf(t1x, t2x), fmaxf(fminf(t1y, t2y), fminf(t1z, t2z)));
    float tmax = fminf(fmaxf(t1x, t2x), fminf(fmaxf(t1y, t2y), fmaxf(t1z, t2z)));
    bool hit = tmin < tmax;
    float t0 = fmaxf(hit ? tmin : 0.0f, 0.0f);

    // raypos = campos + raydir * t0 (unfused, matches reference rounding)
    float posx = __fadd_rn(cx, __fmul_rn(dx, t0));
    float posy = __fadd_rn(cy, __fmul_rn(dy, t0));
    float posz = __fadd_rn(cz, __fmul_rn(dz, t0));

    // per-step increment raydir*DT (reference recomputes; same rounded value)
    float sx = __fmul_rn(dx, DT);
    float sy = __fmul_rn(dy, DT);
    float sz = __fmul_rn(dz, DT);

    float r_out = 0.0f, g_out = 0.0f, b_out = 0.0f, a_out = 0.0f;

    if (hit) {
        const uint2* __restrict__ vb = g_vol + (long)b * D3;
        // steps beyond kmax are geometrically invalid (validated R4/R5)
        int kmax = (int)((tmax - t0) * 32.0f) + 3;
        if (kmax > NSTEPS) kmax = NSTEPS;

        int rc = 0;  // confirmed chunk count for this batch
        Stage stA, stB;
        prep_step(vb, posx, posy, posz, stA, rc, b);

        #pragma unroll 1
        for (int k = 0; k < kmax; k += 2) {
            posx = __fadd_rn(posx, sx);
            posy = __fadd_rn(posy, sy);
            posz = __fadd_rn(posz, sz);
            prep_step(vb, posx, posy, posz, stB, rc, b);
            consume(stA, r_out, g_out, b_out, a_out);

            posx = __fadd_rn(posx, sx);
            posy = __fadd_rn(posy, sy);
            posz = __fadd_rn(posz, sz);
            prep_step(vb, posx, posy, posz, stA, rc, b);
            consume(stB, r_out, g_out, b_out, a_out);

            if (a_out >= 1.0f) break;  // exactly 1 -> future contribs 0
        }
    }

    long obase = (((long)b * 4) * HH + y) * WW + x;
    const long cstride = (long)HH * WW;
    out[obase + 0 * cstride] = r_out;
    out[obase + 1 * cstride] = g_out;
    out[obase + 2 * cstride] = b_out;
    out[obase + 3 * cstride] = a_out;
}

// ---------------------------------------------------------------------------
// Launch: z-slab producer/consumer pipeline.
//   stream0: reset -> raymarch (full grid; self-syncs on slab flags)
//   s_hi:    (after reset) interleave, high priority, 1 block/SM via smem cap
//   stream0: waits il-done event (join; rm already waits via flags)
// ---------------------------------------------------------------------------
#define IL_SMEM (120 * 1024)

extern "C" void kernel_launch(void* const* d_in, const int* in_sizes, int n_in,
                              void* d_out, int out_size) {
    const float* camrot      = (const float*)d_in[0];
    const float* campos      = (const float*)d_in[1];
    const float* focal       = (const float*)d_in[2];
    const float* princpt     = (const float*)d_in[3];
    const float* pixelcoords = (const float*)d_in[4];
    const float* volume      = (const float*)d_in[5];
    float* out = (float*)d_out;

    // One-time handle creation (first call is the uncaptured correctness
    // run, so creation happens outside graph capture; replays reuse).
    static cudaStream_t s_hi = nullptr;
    static cudaEvent_t evA = nullptr, evB = nullptr;
    if (s_hi == nullptr) {
        int lo_p, hi_p;
        cudaDeviceGetStreamPriorityRange(&lo_p, &hi_p);
        cudaStreamCreateWithPriority(&s_hi, cudaStreamNonBlocking, hi_p);
        cudaEventCreateWithFlags(&evA, cudaEventDisableTiming);
        cudaEventCreateWithFlags(&evB, cudaEventDisableTiming);
        cudaFuncSetAttribute(interleave_kernel,
                             cudaFuncAttributeMaxDynamicSharedMemorySize,
                             IL_SMEM);
    }

    // stream0: per-replay flag targets
    reset_kernel<<<1, 32>>>();
    cudaEventRecord(evA, 0);

    // s_hi: producer (after reset so its adds land on this replay's epoch)
    cudaStreamWaitEvent(s_hi, evA, 0);
    interleave_kernel<<<16 * BLKS_PER_CHUNK, 256, IL_SMEM, s_hi>>>(
        (const float4*)volume);
    cudaEventRecord(evB, s_hi);

    // stream0: consumer (concurrent with producer; flag-synchronized)
    {
        dim3 block(8, 8, 1);
        dim3 grid(WW / 8, HH / 8, BB);
        raymarch_kernel<<<grid, block>>>(camrot, campos, focal, princpt,
                                         pixelcoords, out);
    }

    // join producer branch back into the capture-origin stream
    cudaStreamWaitEvent(0, evB, 0);
}

// round 16
// speedup vs baseline: 2.1588x; 2.1588x over previous
#include <cuda_runtime.h>
#include <cuda_fp16.h>
#include <math.h>

// Problem constants (from reference setup_inputs)
#define BB 2
#define HH 256
#define WW 256
#define DD 128
#define D3 (DD * DD * DD)
#define DT 0.03125f
#define NSTEPS 111

// Non-redundant half4 volume: entry i (8 B uint2) = voxel i's 4 channels in
// fp16: (r,g),(b,a). Corner loads are LDG.64; x-adjacent corners are
// contiguous. Padded by DD*DD+DD+1 zero-initialized entries so
// unclamped-neighbor addresses (x0/y0/z0 clamped to <=127 only) stay in
// bounds; such entries are only ever multiplied by exactly-zero weights.
__device__ uint2 g_vol[BB * D3 + DD * DD + DD + 1];

__device__ __forceinline__ unsigned pack2h(float lo, float hi) {
    __half2 h = __floats2half2_rn(lo, hi);
    return *reinterpret_cast<unsigned*>(&h);
}

// ---------------------------------------------------------------------------
// Pass 1: interleave + fp16-pack ONE batch. Each thread packs 4 voxels (one
// float4 per channel) into two contiguous uint4 stores. Input is read with
// __ldcs (evict-first): the 64 MB fp32 stream is read-once, and keeping it
// out of L2 preserves the freshly written fp16 volume for the raymarch pass.
// ---------------------------------------------------------------------------
__global__ void interleave_kernel(const float4* __restrict__ vol4, int b) {
    const int QP = D3 / 4;
    int s4 = blockIdx.x * blockDim.x + threadIdx.x;
    if (s4 >= QP) return;
    const float4* base4 = vol4 + (long)b * 4 * QP;
    float4 c0 = __ldcs(base4 + 0 * QP + s4);
    float4 c1 = __ldcs(base4 + 1 * QP + s4);
    float4 c2 = __ldcs(base4 + 2 * QP + s4);
    float4 c3 = __ldcs(base4 + 3 * QP + s4);

    uint4* outp = reinterpret_cast<uint4*>(g_vol) + ((long)b * D3 / 2 + (long)s4 * 2);
    uint4 u0, u1;
    u0.x = pack2h(c0.x, c1.x); u0.y = pack2h(c2.x, c3.x);   // voxel 4*s4+0
    u0.z = pack2h(c0.y, c1.y); u0.w = pack2h(c2.y, c3.y);   // voxel 4*s4+1
    u1.x = pack2h(c0.z, c1.z); u1.y = pack2h(c2.z, c3.z);   // voxel 4*s4+2
    u1.z = pack2h(c0.w, c1.w); u1.w = pack2h(c2.w, c3.w);   // voxel 4*s4+3
    outp[0] = u0;
    outp[1] = u1;
}

// One pipeline stage: validity, fractions, 8 in-flight corner loads.
struct Stage {
    bool valid;
    float fx, fy, fz;
    uint2 U000, U001, U010, U011, U100, U101, U110, U111;
};

__device__ __forceinline__ void prep_step(
    const uint2* __restrict__ vb,
    float pxp, float pyp, float pzp, Stage& st) {
    // valid  <=>  (-1 < p < 1) on all axes  <=>  max|p| < 1   (exact)
    float m = fmaxf(fmaxf(fabsf(pxp), fabsf(pyp)), fabsf(pzp));
    st.valid = m < 1.0f;
    float gx = fmaf(pxp, 63.5f, 63.5f);
    float gy = fmaf(pyp, 63.5f, 63.5f);
    float gz = fmaf(pzp, 63.5f, 63.5f);
    // single unsigned clamp per axis: negative -> huge -> 127.
    // Valid positions give [0,127]; index 127 is only reachable with a
    // fraction of exactly 0, so padded/neighbor entries are multiplied by
    // exactly-zero weights.
    int x0 = (int)min((unsigned)__float2int_rd(gx), 127u);
    int y0 = (int)min((unsigned)__float2int_rd(gy), 127u);
    int z0 = (int)min((unsigned)__float2int_rd(gz), 127u);
    st.fx = gx - (float)x0;
    st.fy = gy - (float)y0;
    st.fz = gz - (float)z0;
    int base = (((z0 << 7) + y0) << 7) + x0;
    st.U000 = __ldg(vb + base);
    st.U001 = __ldg(vb + base + 1);
    st.U010 = __ldg(vb + base + DD);
    st.U011 = __ldg(vb + base + DD + 1);
    st.U100 = __ldg(vb + base + DD * DD);
    st.U101 = __ldg(vb + base + DD * DD + 1);
    st.U110 = __ldg(vb + base + DD * DD + DD);
    st.U111 = __ldg(vb + base + DD * DD + DD + 1);
}

__device__ __forceinline__ __half2 h2_of(unsigned u) {
    return *reinterpret_cast<const __half2*>(&u);
}

// half2 lerp: a + t*(b-a)
__device__ __forceinline__ __half2 h2lerp(__half2 a, __half2 b, __half2 t) {
    return __hfma2(t, __hsub2(b, a), a);
}

// Branchless consume: fp16 lerp-tree trilerp (x, then y, then z) + fp32
// compositing. The alpha chain is bit-exact unfused _rn (it gates
// saturation); rgb accumulators are smooth terminal outputs, so FFMA
// contraction there is harmless. Contribution gated by validity via one
// select; invalid steps add exact zeros.
__device__ __forceinline__ void consume(const Stage& st,
                                        float& r_out, float& g_out,
                                        float& b_out, float& a_out) {
    __half2 fxh = __float2half2_rn(st.fx);
    __half2 fyh = __float2half2_rn(st.fy);
    __half2 fzh = __float2half2_rn(st.fz);

    // x-lerp between adjacent corner voxels (rg and ba ride together)
    __half2 c00rg = h2lerp(h2_of(st.U000.x), h2_of(st.U001.x), fxh);
    __half2 c00ba = h2lerp(h2_of(st.U000.y), h2_of(st.U001.y), fxh);
    __half2 c01rg = h2lerp(h2_of(st.U010.x), h2_of(st.U011.x), fxh);
    __half2 c01ba = h2lerp(h2_of(st.U010.y), h2_of(st.U011.y), fxh);
    __half2 c10rg = h2lerp(h2_of(st.U100.x), h2_of(st.U101.x), fxh);
    __half2 c10ba = h2lerp(h2_of(st.U100.y), h2_of(st.U101.y), fxh);
    __half2 c11rg = h2lerp(h2_of(st.U110.x), h2_of(st.U111.x), fxh);
    __half2 c11ba = h2lerp(h2_of(st.U110.y), h2_of(st.U111.y), fxh);
    // y-lerp
    __half2 c0rg = h2lerp(c00rg, c01rg, fyh);
    __half2 c0ba = h2lerp(c00ba, c01ba, fyh);
    __half2 c1rg = h2lerp(c10rg, c11rg, fyh);
    __half2 c1ba = h2lerp(c10ba, c11ba, fyh);
    // z-lerp
    float2 rg = __half22float2(h2lerp(c0rg, c1rg, fzh));
    float2 ba = __half22float2(h2lerp(c0ba, c1ba, fzh));

    float contrib = __fsub_rn(
        fminf(__fadd_rn(a_out, __fmul_rn(ba.y, DT)), 1.0f), a_out);
    contrib = st.valid ? contrib : 0.0f;   // single select, no branch
    r_out = fmaf(rg.x, contrib, r_out);    // smooth: FFMA ok
    g_out = fmaf(rg.y, contrib, g_out);
    b_out = fmaf(ba.x, contrib, b_out);
    a_out = __fadd_rn(a_out, contrib);     // exact: gates saturation
}

// ---------------------------------------------------------------------------
// Pass 2: ray march ONE batch, depth-1 prefetch with ping-pong stages.
// One thread per pixel; 64-thread (8x8) blocks for fine-grained drain of
// variable-length rays. Ray setup + position stepping replicate the
// reference's IEEE fp32 ops bit-exactly (unfused _rn intrinsics): step-0
// validity is a knife-edge (entry position lies exactly on the cube face).
// Downstream of a valid position everything is smooth. Saturation is checked
// once per unrolled pair: after alpha reaches exactly 1.0 every later
// contribution is exactly 0, so deferring the break is bit-safe. Phantom
// steps past kmax are geometrically invalid by a margin far above fp drift.
// Output stores use __stcs (streaming) so the write-once image does not
// evict the L2-resident volume.
// ---------------------------------------------------------------------------
__global__ void __launch_bounds__(64, 14)
raymarch_kernel(const float* __restrict__ camrot,
                const float* __restrict__ campos,
                const float* __restrict__ focal,
                const float* __restrict__ princpt,
                const float* __restrict__ pixelcoords,
                float* __restrict__ out, int b) {
    int x = blockIdx.x * blockDim.x + threadIdx.x;
    int y = blockIdx.y * blockDim.y + threadIdx.y;

    // --- camera ray (bit-exact vs reference) ---
    long pidx = (((long)b * HH + y) * WW + x) * 2;
    float px = pixelcoords[pidx + 0];
    float py = pixelcoords[pidx + 1];
    float rx = __fdiv_rn(__fsub_rn(px, princpt[b * 2 + 0]), focal[b * 2 + 0]);
    float ry = __fdiv_rn(__fsub_rn(py, princpt[b * 2 + 1]), focal[b * 2 + 1]);
    float rz = 1.0f;
    const float* R = camrot + b * 9;  // dir_j = sum_i R[i][j] * r_i
    float dx = __fadd_rn(__fadd_rn(__fmul_rn(R[0], rx), __fmul_rn(R[3], ry)),
                         __fmul_rn(R[6], rz));
    float dy = __fadd_rn(__fadd_rn(__fmul_rn(R[1], rx), __fmul_rn(R[4], ry)),
                         __fmul_rn(R[7], rz));
    float dz = __fadd_rn(__fadd_rn(__fmul_rn(R[2], rx), __fmul_rn(R[5], ry)),
                         __fmul_rn(R[8], rz));
    float n2 = __fadd_rn(__fadd_rn(__fmul_rn(dx, dx), __fmul_rn(dy, dy)),
                         __fmul_rn(dz, dz));
    float nrm = sqrtf(n2);
    dx = __fdiv_rn(dx, nrm);
    dy = __fdiv_rn(dy, nrm);
    dz = __fdiv_rn(dz, nrm);

    float cx = campos[b * 3 + 0];
    float cy = campos[b * 3 + 1];
    float cz = campos[b * 3 + 2];

    // --- AABB [-1,1]^3 intersection (IEEE divisions; inf semantics ok) ---
    float t1x = __fdiv_rn(__fsub_rn(-1.0f, cx), dx);
    float t2x = __fdiv_rn(__fsub_rn( 1.0f, cx), dx);
    float t1y = __fdiv_rn(__fsub_rn(-1.0f, cy), dy);
    float t2y = __fdiv_rn(__fsub_rn( 1.0f, cy), dy);
    float t1z = __fdiv_rn(__fsub_rn(-1.0f, cz), dz);
    float t2z = __fdiv_rn(__fsub_rn( 1.0f, cz), dz);
    float tmin = fmaxf(fminf(t1x, t2x), fmaxf(fminf(t1y, t2y), fminf(t1z, t2z)));
    float tmax = fminf(fmaxf(t1x, t2x), fminf(fmaxf(t1y, t2y), fmaxf(t1z, t2z)));
    bool hit = tmin < tmax;
    float t0 = fmaxf(hit ? tmin : 0.0f, 0.0f);

    // raypos = campos + raydir * t0 (unfused, matches reference rounding)
    float posx = __fadd_rn(cx, __fmul_rn(dx, t0));
    float posy = __fadd_rn(cy, __fmul_rn(dy, t0));
    float posz = __fadd_rn(cz, __fmul_rn(dz, t0));

    // per-step increment raydir*DT (reference recomputes; same rounded value)
    float sx = __fmul_rn(dx, DT);
    float sy = __fmul_rn(dy, DT);
    float sz = __fmul_rn(dz, DT);

    float r_out = 0.0f, g_out = 0.0f, b_out = 0.0f, a_out = 0.0f;

    if (hit) {
        const uint2* __restrict__ vb = g_vol + (long)b * D3;
        // steps beyond kmax are geometrically invalid (validated R4/R5)
        int kmax = (int)((tmax - t0) * 32.0f) + 3;
        if (kmax > NSTEPS) kmax = NSTEPS;

        Stage stA, stB;
        prep_step(vb, posx, posy, posz, stA);

        #pragma unroll 1
        for (int k = 0; k < kmax; k += 2) {
            posx = __fadd_rn(posx, sx);
            posy = __fadd_rn(posy, sy);
            posz = __fadd_rn(posz, sz);
            prep_step(vb, posx, posy, posz, stB);
            consume(stA, r_out, g_out, b_out, a_out);

            posx = __fadd_rn(posx, sx);
            posy = __fadd_rn(posy, sy);
            posz = __fadd_rn(posz, sz);
            prep_step(vb, posx, posy, posz, stA);
            consume(stB, r_out, g_out, b_out, a_out);

            // saturated alpha is exactly 1.0 -> all future contribs 0
            if (a_out >= 1.0f) break;
        }
    }

    long obase = (((long)b * 4) * HH + y) * WW + x;
    const long cstride = (long)HH * WW;
    __stcs(out + obase + 0 * cstride, r_out);
    __stcs(out + obase + 1 * cstride, g_out);
    __stcs(out + obase + 2 * cstride, b_out);
    __stcs(out + obase + 3 * cstride, a_out);
}

// ---------------------------------------------------------------------------
// Launch: pipeline the two independent batches across streams (R13 schedule).
//   legacy: interleave(b0) -> ev1 -> raymarch(b0)
//   s2:     wait ev1 -> interleave(b1) -> raymarch(b1) -> ev2
//   legacy: wait ev2
// interleave(b1) (LTS-bound) overlaps raymarch(b0); the two raymarch halves
// co-reside. Batch b's raymarch touches batch (1-b)'s g_vol region only
// through weight-0 clamped neighbor loads; every value that region can hold
// is a finite fp16 pack, and finite*0 contributes exactly 0, so the overlap
// is race-free in output bits.
// ---------------------------------------------------------------------------
extern "C" void kernel_launch(void* const* d_in, const int* in_sizes, int n_in,
                              void* d_out, int out_size) {
    const float* camrot      = (const float*)d_in[0];
    const float* campos      = (const float*)d_in[1];
    const float* focal       = (const float*)d_in[2];
    const float* princpt     = (const float*)d_in[3];
    const float* pixelcoords = (const float*)d_in[4];
    const float* volume      = (const float*)d_in[5];
    float* out = (float*)d_out;

    // One-time handle creation (first call is the uncaptured correctness
    // run, so creation happens outside graph capture; replays reuse).
    static cudaStream_t s2 = nullptr;
    static cudaEvent_t ev1 = nullptr, ev2 = nullptr;
    if (s2 == nullptr) {
        cudaStreamCreateWithFlags(&s2, cudaStreamNonBlocking);
        cudaEventCreateWithFlags(&ev1, cudaEventDisableTiming);
        cudaEventCreateWithFlags(&ev2, cudaEventDisableTiming);
    }

    const int QP = D3 / 4;
    int ithreads = 256;
    int iblocks = (QP + ithreads - 1) / ithreads;
    dim3 rblock(8, 8, 1);
    dim3 rgrid(WW / 8, HH / 8, 1);

    // legacy stream: batch 0
    interleave_kernel<<<iblocks, ithreads>>>((const float4*)volume, 0);
    cudaEventRecord(ev1, 0);
    raymarch_kernel<<<rgrid, rblock>>>(camrot, campos, focal, princpt,
                                       pixelcoords, out, 0);

    // s2: batch 1 (forked after interleave(b0) to keep LTS phases separate)
    cudaStreamWaitEvent(s2, ev1, 0);
    interleave_kernel<<<iblocks, ithreads, 0, s2>>>((const float4*)volume, 1);
    raymarch_kernel<<<rgrid, rblock, 0, s2>>>(camrot, campos, focal, princpt,
                                              pixelcoords, out, 1);
    cudaEventRecord(ev2, s2);

    // join back to the capture-origin stream
    cudaStreamWaitEvent(0, ev2, 0);
}